// round 17
// baseline (speedup 1.0000x reference)
#include <cuda_runtime.h>
#include <math.h>

// Problem dims (fixed by the dataset): x[512,256], W[256,256], b[256], lut[33,33], N=32
#define MM 512
#define KK 256
#define OO 256

// -------- device scratch (no allocations allowed) --------
__device__ unsigned g_pA[128];               // per-block partial max |x| bits
__device__ unsigned g_pD[128];               // per-block partial max |W|,|b| bits
__device__ float    g_snf[2];                // [0]=sn2, [1]=sn1 (published by quant block 0)
__device__ int      g_cc[OO];                // cc = (int)(sanit(b)*sn1)
__device__ __align__(16) int g_Ak[KK * MM];      // k-major: aa[k][m]
__device__ __align__(16) int g_Bk[KK * OO * 2];  // k-major int2: (bb, c)[k][o], c = 31*[bb<0]

__device__ __forceinline__ float sanit(float v) {
    if (isnan(v)) return 0.0f;
    if (isinf(v)) return 1.0f;   // jnp.where(isinf, ones_like)
    return v;
}

__device__ __forceinline__ unsigned absbits(float v) {
    return __float_as_uint(fabsf(sanit(v)));
}

// sn = 2^floor(log2(floor(32/m))) with m==0 -> 1, exactly (powers of two).
__device__ __forceinline__ float scale_of(unsigned bits) {
    float m = __uint_as_float(bits);
    if (m == 0.0f) m = 1.0f;
    float fn = floorf(32.0f / m);
    if (!(fn >= 1.0f)) return 0.0f;
    int e = ilogbf(fn);
    return ldexpf(1.0f, e);
}

// Branch-light max-reduce: every thread issues 1-3 independent float4 loads
// up front (one DRAM latency for the whole kernel), REDUX warp reduction,
// tiny smem tree across 8 warps, partials to global (no atomics, no init).
__global__ void __launch_bounds__(256) k_reduce(const float* __restrict__ x,
                                                const float* __restrict__ W,
                                                const float* __restrict__ b) {
    __shared__ unsigned sA[8], sD[8];
    const int t = blockIdx.x * 256 + threadIdx.x;   // 0..32767

    const float4 a = ((const float4*)x)[t];         // 512*256/4 == 32768 exactly
    unsigned la = max(max(absbits(a.x), absbits(a.y)),
                      max(absbits(a.z), absbits(a.w)));
    unsigned ld = 0u;
    if (t < (OO * KK / 4)) {                        // 16384 float4 of W
        const float4 w = ((const float4*)W)[t];
        ld = max(max(absbits(w.x), absbits(w.y)),
                 max(absbits(w.z), absbits(w.w)));
    }
    if (t < (OO / 4)) {                             // 64 float4 of b
        const float4 bb = ((const float4*)b)[t];
        ld = max(ld, max(max(absbits(bb.x), absbits(bb.y)),
                         max(absbits(bb.z), absbits(bb.w))));
    }

    la = __reduce_max_sync(0xffffffffu, la);
    ld = __reduce_max_sync(0xffffffffu, ld);

    const int wid = threadIdx.x >> 5;
    if ((threadIdx.x & 31) == 0) { sA[wid] = la; sD[wid] = ld; }
    __syncthreads();
    if (threadIdx.x == 0) {
        unsigned ma = sA[0], md = sD[0];
#pragma unroll
        for (int i = 1; i < 8; i++) { ma = max(ma, sA[i]); md = max(md, sD[i]); }
        g_pA[blockIdx.x] = ma;
        g_pD[blockIdx.x] = md;
    }
}

// Fused quantize + transpose, vectorized. Blocks 0-127: x -> g_Ak (32x32 tiles,
// float4 in / int4 out). Blocks 128-191: W -> g_Bk int2 (bb, c). Block 128 also
// quantizes b -> g_cc.
__global__ void __launch_bounds__(256) k_quant(const float* __restrict__ x,
                                               const float* __restrict__ W,
                                               const float* __restrict__ b) {
    __shared__ unsigned rA[128], rD[128];
    __shared__ float s_sn[2];
    __shared__ int s_t[32][33];

    const int tid = threadIdx.x;
    if (tid < 128) { rA[tid] = g_pA[tid]; rD[tid] = g_pD[tid]; }
    __syncthreads();
    for (int s = 64; s > 0; s >>= 1) {
        if (tid < s) {
            rA[tid] = max(rA[tid], rA[tid + s]);
            rD[tid] = max(rD[tid], rD[tid + s]);
        }
        __syncthreads();
    }
    if (tid == 0) {
        s_sn[0] = scale_of(rA[0]);   // sn2
        s_sn[1] = scale_of(rD[0]);   // sn1
        if (blockIdx.x == 0) { g_snf[0] = s_sn[0]; g_snf[1] = s_sn[1]; }
    }
    __syncthreads();
    const float sn2 = s_sn[0], sn1 = s_sn[1];

    const int bid = blockIdx.x;

    if (bid < 128) {
        const int m0 = (bid >> 3) * 32, k0 = (bid & 7) * 32;
        // Load: thread -> one float4 (row r, cols 4q..4q+3). Conflict-free writes.
        {
            const int r = tid >> 3, q = tid & 7;
            const float4 v = *(const float4*)&x[(m0 + r) * KK + k0 + 4 * q];
            s_t[r][4 * q + 0] = (int)(sanit(v.x) * sn2);
            s_t[r][4 * q + 1] = (int)(sanit(v.y) * sn2);
            s_t[r][4 * q + 2] = (int)(sanit(v.z) * sn2);
            s_t[r][4 * q + 3] = (int)(sanit(v.w) * sn2);
        }
        __syncthreads();
        // Store transposed: thread -> int4 of 4 consecutive m at row k0+kk.
        {
            const int kk = tid >> 3, j = tid & 7;
            int4 o;
            o.x = s_t[4 * j + 0][kk];
            o.y = s_t[4 * j + 1][kk];
            o.z = s_t[4 * j + 2][kk];
            o.w = s_t[4 * j + 3][kk];
            *(int4*)&g_Ak[(k0 + kk) * MM + m0 + 4 * j] = o;
        }
    } else {
        const int idx = bid - 128;
        const int o0 = (idx >> 3) * 32, k0 = (idx & 7) * 32;
        {
            const int r = tid >> 3, q = tid & 7;
            const float4 v = *(const float4*)&W[(o0 + r) * KK + k0 + 4 * q];
            s_t[r][4 * q + 0] = (int)(sanit(v.x) * sn1);
            s_t[r][4 * q + 1] = (int)(sanit(v.y) * sn1);
            s_t[r][4 * q + 2] = (int)(sanit(v.z) * sn1);
            s_t[r][4 * q + 3] = (int)(sanit(v.w) * sn1);
        }
        __syncthreads();
        // 512 int4 slots (kk 0..31 x o-pair j 0..15), 2 per thread.
#pragma unroll
        for (int it = 0; it < 2; it++) {
            const int s = tid + 256 * it;
            const int kk = s >> 4, j = s & 15;
            const int bb0 = s_t[2 * j][kk];
            const int bb1 = s_t[2 * j + 1][kk];
            int4 o;
            o.x = bb0; o.y = (bb0 < 0) ? 31 : 0;
            o.z = bb1; o.w = (bb1 < 0) ? 31 : 0;
            ((int4*)g_Bk)[(((k0 + kk) * OO + o0) >> 1) + j] = o;
        }
        if (bid == 128) {
            g_cc[tid] = (int)(sanit(b[tid]) * sn1);
        }
    }
}

// GEMM: x9[m,o] = sum_k (aa*bb + c) >> 5   (exact trunc semantics, aa >= 0).
// Tile 32(m) x 32(o), 256 threads, 2x2 micro-tile, K staged in two 128-chunks
// (48KB static smem). Inner loop: LDS.64 (A pair) + LDS.128 (B pair) +
// 4x(IMAD + SHF + IADD).
__global__ void __launch_bounds__(256) k_gemm(float* __restrict__ out) {
    __shared__ int  sA[128][32];   // 16KB: aa[k][m]
    __shared__ int2 sB[128][32];   // 32KB: (bb,c)[k][o]

    const int tid = threadIdx.x;
    const int o0 = blockIdx.x * 32;
    const int m0 = blockIdx.y * 32;
    const int ty = tid >> 4, tx = tid & 15;

    int acc00 = 0, acc01 = 0, acc10 = 0, acc11 = 0;

#pragma unroll 1
    for (int half = 0; half < 2; half++) {
        const int kb = half * 128;
        // Stage A: 128 k x 32 m ints = 1024 int4 (pure 16B copies)
        for (int i = tid; i < 1024; i += 256) {
            const int k = i >> 3, j = i & 7;
            ((int4*)sA)[i] = *(const int4*)&g_Ak[(kb + k) * MM + m0 + 4 * j];
        }
        // Stage B: 128 k x 32 int2 = 2048 int4
        for (int i = tid; i < 2048; i += 256) {
            const int k = i >> 4, j = i & 15;
            ((int4*)sB)[i] = *(const int4*)&g_Bk[(kb + k) * (OO * 2) + o0 * 2 + 4 * j];
        }
        __syncthreads();

#pragma unroll 16
        for (int k = 0; k < 128; k++) {
            const int2 a  = *(const int2*)&sA[k][2 * ty];
            const int4 bq = *(const int4*)&sB[k][2 * tx];
            acc00 += (a.x * bq.x + bq.y) >> 5;
            acc01 += (a.x * bq.z + bq.w) >> 5;
            acc10 += (a.y * bq.x + bq.y) >> 5;
            acc11 += (a.y * bq.z + bq.w) >> 5;
        }
        __syncthreads();
    }

    // Epilogue: d = trunc(x9/sn2) + cc ; out = d / sn1  (exact power-of-two ops)
    const float sn2 = g_snf[0];
    const float sn1 = g_snf[1];
    const int m = m0 + 2 * ty, o = o0 + 2 * tx;
    const int c0 = g_cc[o], c1 = g_cc[o + 1];

    int d;
    d = (int)((float)acc00 / sn2) + c0;
    out[m * OO + o]           = (float)d / sn1;
    d = (int)((float)acc01 / sn2) + c1;
    out[m * OO + o + 1]       = (float)d / sn1;
    d = (int)((float)acc10 / sn2) + c0;
    out[(m + 1) * OO + o]     = (float)d / sn1;
    d = (int)((float)acc11 / sn2) + c1;
    out[(m + 1) * OO + o + 1] = (float)d / sn1;
}

extern "C" void kernel_launch(void* const* d_in, const int* in_sizes, int n_in,
                              void* d_out, int out_size) {
    const float* x = (const float*)d_in[0];   // [512,256]
    const float* W = (const float*)d_in[1];   // [256,256]
    const float* b = (const float*)d_in[2];   // [256]
    // d_in[3] = lut, unused: lut[i][j] == (i*j)>>5, computed inline.
    float* out = (float*)d_out;               // [512,256]

    k_reduce<<<128, 256>>>(x, W, b);
    k_quant<<<192, 256>>>(x, W, b);
    dim3 grid(OO / 32, MM / 32);              // 8 x 16 = 128 blocks
    k_gemm<<<grid, 256>>>(out);
}